// round 10
// baseline (speedup 1.0000x reference)
#include <cuda_runtime.h>
#include <cstdint>

#define N_NODES   100000
#define FDIM      64
#define MAX_E     1250000
#define SCAN_BLK  1024                 // elements per scan block (256 thr x 4)
#define MAX_SB    128                  // max scan blocks (98 used)

typedef unsigned long long ull;

// ---------------- scratch (static __device__) ----------------
__device__ float4 g_xw4[(size_t)N_NODES * 16];   // dis-premultiplied x@W rows
__device__ float4 g_h4 [(size_t)N_NODES * 16];   // layer-1 result
__device__ float  g_dis[N_NODES];
__device__ int    g_cnt[N_NODES];                // in-degree histogram (zero-invariant)
__device__ int    g_rowstart[N_NODES + 1];       // CSR row offsets
__device__ int    g_cursor[N_NODES];             // fill cursors
__device__ int    g_csr[MAX_E];                  // CSR src indices
__device__ int    g_flag[MAX_SB];                // lookback flags (zero-invariant)

// ---------------- per-block dtype probe ----------------
__device__ __forceinline__ int probe_is64(const int* ei32, int* sflag) {
    if (threadIdx.x == 0) {
        int allz = 1;
        #pragma unroll
        for (int k = 0; k < 64; k++)
            if (ei32[2 * k + 1] != 0) { allz = 0; break; }
        *sflag = allz;
    }
    __syncthreads();
    return *sflag;
}

// ---------------- histogram of dst ----------------
__global__ void k_hist(const int* __restrict__ ei32, int E, int n) {
    __shared__ int sis64;
    int is64 = probe_is64(ei32, &sis64);
    int e = blockIdx.x * blockDim.x + threadIdx.x;
    if (e < E) {
        int d;
        if (is64) d = (int)((const long long*)ei32)[(size_t)E + e];
        else      d = ei32[(size_t)E + e];
        d = d < 0 ? 0 : (d >= n ? n - 1 : d);
        atomicAdd(&g_cnt[d], 1);
    }
}

// ------ single-pass scan (decoupled lookback): dis + rowstart + cursor -----
__global__ __launch_bounds__(256) void k_scan(int n, int E) {
    __shared__ int s[256];
    __shared__ int sbase;
    const int t   = threadIdx.x;
    const int bid = blockIdx.x;
    const int i0  = bid * SCAN_BLK + t * 4;

    int c[4];
    int sum = 0;
    #pragma unroll
    for (int k = 0; k < 4; k++) {
        int i = i0 + k;
        c[k] = (i < n) ? g_cnt[i] : 0;
        sum += c[k];
        if (i < n) g_dis[i] = rsqrtf((float)c[k] + 1.0f);   // +1 self-loop
    }

    s[t] = sum;
    __syncthreads();
    for (int off = 1; off < 256; off <<= 1) {
        int a = (t >= off) ? s[t - off] : 0;
        __syncthreads();
        s[t] += a;
        __syncthreads();
    }
    int myIncl = s[t];
    int total  = s[255];

    if (t == 0) atomicExch(&g_flag[bid], total + 1);

    int part = 0;
    if (t < bid) {
        int v;
        do { v = atomicAdd(&g_flag[t], 0); } while (v == 0);
        part = v - 1;
    }
    __syncthreads();
    s[t] = part;
    __syncthreads();
    for (int off = 128; off > 0; off >>= 1) {
        if (t < off) s[t] += s[t + off];
        __syncthreads();
    }
    if (t == 0) {
        sbase = s[0];
        if (bid == 0) g_rowstart[n] = E;
    }
    __syncthreads();

    int base = sbase + myIncl - sum;
    #pragma unroll
    for (int k = 0; k < 4; k++) {
        int i = i0 + k;
        if (i < n) {
            g_rowstart[i] = base;
            g_cursor[i]   = base;
            base += c[k];
        }
    }
}

// -------- CSR fill + reset zero-invariants (cnt, flags) for next replay ----
__global__ void k_fill(const int* __restrict__ ei32, int E, int n) {
    __shared__ int sis64;
    int is64 = probe_is64(ei32, &sis64);
    int e = blockIdx.x * blockDim.x + threadIdx.x;
    if (e < E) {
        int s, d;
        if (is64) {
            const long long* ei64 = (const long long*)ei32;
            s = (int)ei64[e];
            d = (int)ei64[(size_t)E + e];
        } else {
            s = ei32[e];
            d = ei32[(size_t)E + e];
        }
        s = s < 0 ? 0 : (s >= n ? n - 1 : s);
        d = d < 0 ? 0 : (d >= n ? n - 1 : d);
        int pos = atomicAdd(&g_cursor[d], 1);
        g_csr[pos] = s;
        g_cnt[d]   = 0;
    }
    if (e < MAX_SB) g_flag[e] = 0;
}

// -------- GEMM (f32x2, 4x8 per-thread tile, 256 threads, occ-tuned) --------
// block: 256 threads, tile 128 rows x 64 cols. thread = rows {ty+32i} x 8 cols.
__global__ __launch_bounds__(256, 3) void k_gemm(
    const float* __restrict__ in_ext, int in_is_h,
    const float* __restrict__ W, int relu, int n)
{
    const float* in = in_is_h ? (const float*)g_h4 : in_ext;
    float*       xw = (float*)g_xw4;

    __shared__ float sW[64 * 64];
    __shared__ float sx[128][66];

    const int tid  = threadIdx.x;
    const int row0 = blockIdx.x * 128;

    // fill W (float4): 1024 float4 / 256 threads = 4 each
    {
        const float4* W4  = (const float4*)W;
        float4*       sW4 = (float4*)sW;
        #pragma unroll
        for (int i = 0; i < 4; i++) sW4[tid + i * 256] = W4[tid + i * 256];
    }
    // fill x: 2048 float4 / 256 threads = 8 each
    for (int idx = tid; idx < 128 * 16; idx += 256) {
        int r  = idx >> 4;
        int c4 = (idx & 15) * 4;
        int gr = row0 + r;
        float4 v = make_float4(0.f, 0.f, 0.f, 0.f);
        if (gr < n) v = *(const float4*)&in[(size_t)gr * 64 + c4];
        if (relu) {
            v.x = fmaxf(v.x, 0.f); v.y = fmaxf(v.y, 0.f);
            v.z = fmaxf(v.z, 0.f); v.w = fmaxf(v.w, 0.f);
        }
        *(float2*)&sx[r][c4]     = make_float2(v.x, v.y);
        *(float2*)&sx[r][c4 + 2] = make_float2(v.z, v.w);
    }
    __syncthreads();

    const int tx = tid & 7;        // col group: 8 cols = 4 pairs
    const int ty = tid >> 3;       // 32 row groups; rows ty, ty+32, ty+64, ty+96
    const int c0 = tx * 8;

    ull a2[4][4];                  // [row][colpair]
    #pragma unroll
    for (int i = 0; i < 4; i++)
        #pragma unroll
        for (int j = 0; j < 4; j++) a2[i][j] = 0ull;

    #pragma unroll 2
    for (int k = 0; k < 64; k += 2) {
        const ull* wp0 = (const ull*)&sW[k * 64 + c0];
        const ull* wp1 = (const ull*)&sW[(k + 1) * 64 + c0];
        ull w00 = wp0[0], w01 = wp0[1], w02 = wp0[2], w03 = wp0[3];
        ull w10 = wp1[0], w11 = wp1[1], w12 = wp1[2], w13 = wp1[3];
        #pragma unroll
        for (int i = 0; i < 4; i++) {
            float2 xv = *(const float2*)&sx[ty + (i << 5)][k];
            ull xb0, xb1;
            asm("mov.b64 %0, {%1,%1};" : "=l"(xb0) : "f"(xv.x));
            asm("mov.b64 %0, {%1,%1};" : "=l"(xb1) : "f"(xv.y));
            asm("fma.rn.f32x2 %0, %1, %2, %0;" : "+l"(a2[i][0]) : "l"(xb0), "l"(w00));
            asm("fma.rn.f32x2 %0, %1, %2, %0;" : "+l"(a2[i][1]) : "l"(xb0), "l"(w01));
            asm("fma.rn.f32x2 %0, %1, %2, %0;" : "+l"(a2[i][2]) : "l"(xb0), "l"(w02));
            asm("fma.rn.f32x2 %0, %1, %2, %0;" : "+l"(a2[i][3]) : "l"(xb0), "l"(w03));
            asm("fma.rn.f32x2 %0, %1, %2, %0;" : "+l"(a2[i][0]) : "l"(xb1), "l"(w10));
            asm("fma.rn.f32x2 %0, %1, %2, %0;" : "+l"(a2[i][1]) : "l"(xb1), "l"(w11));
            asm("fma.rn.f32x2 %0, %1, %2, %0;" : "+l"(a2[i][2]) : "l"(xb1), "l"(w12));
            asm("fma.rn.f32x2 %0, %1, %2, %0;" : "+l"(a2[i][3]) : "l"(xb1), "l"(w13));
        }
    }

    #pragma unroll
    for (int i = 0; i < 4; i++) {
        int gr = row0 + ty + (i << 5);
        if (gr < n) {
            float av[8];
            #pragma unroll
            for (int j = 0; j < 4; j++)
                asm("mov.b64 {%0,%1}, %2;"
                    : "=f"(av[2 * j]), "=f"(av[2 * j + 1]) : "l"(a2[i][j]));
            float dv = g_dis[gr];
            float4 v0 = make_float4(dv * av[0], dv * av[1], dv * av[2], dv * av[3]);
            float4 v1 = make_float4(dv * av[4], dv * av[5], dv * av[6], dv * av[7]);
            *(float4*)&xw[(size_t)gr * 64 + c0]     = v0;
            *(float4*)&xw[(size_t)gr * 64 + c0 + 4] = v1;
        }
    }
}

// ------- CSR gather: out[d] = dis[d]*(row[d] + sum rows[s_j]) + b ----------
__global__ __launch_bounds__(256) void k_gather(
    const float* __restrict__ bias,
    float* __restrict__ out_ext, int out_is_h, int n)
{
    const float4* xw  = g_xw4;
    float4*       out = out_is_h ? g_h4 : (float4*)out_ext;

    int warp = (blockIdx.x * blockDim.x + threadIdx.x) >> 5;
    if (warp >= n) return;
    int lane = threadIdx.x & 31;
    int half = lane >> 4;
    int q    = lane & 15;

    int   rs   = g_rowstart[warp];
    int   re   = g_rowstart[warp + 1];
    float disd = g_dis[warp];

    float4 acc = make_float4(0.f, 0.f, 0.f, 0.f);
    if (half == 0) acc = xw[(size_t)warp * 16 + q];   // self row

    int j = rs + half;
    for (; j + 6 < re; j += 8) {
        int s0 = g_csr[j];
        int s1 = g_csr[j + 2];
        int s2 = g_csr[j + 4];
        int s3 = g_csr[j + 6];
        float4 v0 = xw[(size_t)s0 * 16 + q];
        float4 v1 = xw[(size_t)s1 * 16 + q];
        float4 v2 = xw[(size_t)s2 * 16 + q];
        float4 v3 = xw[(size_t)s3 * 16 + q];
        acc.x += v0.x + v1.x; acc.y += v0.y + v1.y;
        acc.z += v0.z + v1.z; acc.w += v0.w + v1.w;
        acc.x += v2.x + v3.x; acc.y += v2.y + v3.y;
        acc.z += v2.z + v3.z; acc.w += v2.w + v3.w;
    }
    for (; j < re; j += 2) {
        float4 v = xw[(size_t)g_csr[j] * 16 + q];
        acc.x += v.x; acc.y += v.y; acc.z += v.z; acc.w += v.w;
    }
    acc.x += __shfl_xor_sync(0xffffffffu, acc.x, 16);
    acc.y += __shfl_xor_sync(0xffffffffu, acc.y, 16);
    acc.z += __shfl_xor_sync(0xffffffffu, acc.z, 16);
    acc.w += __shfl_xor_sync(0xffffffffu, acc.w, 16);

    if (half == 0) {
        float4 bb = ((const float4*)bias)[q];
        out[(size_t)warp * 16 + q] =
            make_float4(fmaf(disd, acc.x, bb.x), fmaf(disd, acc.y, bb.y),
                        fmaf(disd, acc.z, bb.z), fmaf(disd, acc.w, bb.w));
    }
}

// ---------------- launch ----------------
extern "C" void kernel_launch(void* const* d_in, const int* in_sizes, int n_in,
                              void* d_out, int out_size)
{
    int ix = -1, iei = -1, iw1 = -1, iw2 = -1, ib1 = -1, ib2 = -1;
    for (int i = 0; i < n_in; i++) {
        int s = in_sizes[i];
        if      (s == N_NODES * FDIM) { if (ix  < 0) ix  = i; }
        else if (s == 2 * MAX_E)      { if (iei < 0) iei = i; }
        else if (s == FDIM * FDIM)    { if (iw1 < 0) iw1 = i; else if (iw2 < 0) iw2 = i; }
        else if (s == FDIM)           { if (ib1 < 0) ib1 = i; else if (ib2 < 0) ib2 = i; }
    }
    if (ix < 0 || iei < 0 || iw1 < 0 || iw2 < 0 || ib1 < 0 || ib2 < 0) {
        ix = 0; iei = 1; iw1 = 2; ib1 = 3; iw2 = 4; ib2 = 5;
    }

    const float* x   = (const float*)d_in[ix];
    const int*   ei  = (const int*)d_in[iei];
    const float* W1  = (const float*)d_in[iw1];
    const float* b1  = (const float*)d_in[ib1];
    const float* W2  = (const float*)d_in[iw2];
    const float* b2  = (const float*)d_in[ib2];
    float*       out = (float*)d_out;

    int n = in_sizes[ix] / FDIM;
    int E = in_sizes[iei] / 2;
    if (n > N_NODES) n = N_NODES;
    if (E > MAX_E)   E = MAX_E;

    const int TB = 256;
    const int edgeBlocks = (E + TB - 1) / TB;
    const int gemmBlocks = (n + 127) / 128;
    const int nbScan     = (n + SCAN_BLK - 1) / SCAN_BLK;   // 98 (<= 148 SMs)
    const int gthBlocks  = (n + 7) / 8;

    k_hist<<<edgeBlocks, TB>>>(ei, E, n);                  // launch 0
    k_scan<<<nbScan, 256>>>(n, E);                         // launch 1
    k_fill<<<edgeBlocks, TB>>>(ei, E, n);                  // launch 2

    // layer 1: h = dis*(self + sum rows) + b1, rows = dis*(x@W1)
    k_gemm  <<<gemmBlocks, 256>>>(x, 0, W1, 0, n);         // launch 3
    k_gather<<<gthBlocks, TB>>>(b1, nullptr, 1, n);        // launch 4

    // layer 2: out = dis*(self + sum rows) + b2, rows = dis*(relu(h)@W2)
    k_gemm  <<<gemmBlocks, 256>>>(nullptr, 1, W2, 1, n);   // launch 5 (ncu window)
    k_gather<<<gthBlocks, TB>>>(b2, out, 0, n);            // launch 6
}

// round 13
// speedup vs baseline: 1.1084x; 1.1084x over previous
#include <cuda_runtime.h>
#include <cuda_bf16.h>
#include <cstdint>

#define N_NODES   100000
#define FDIM      64
#define MAX_E     1250000
#define SCAN_BLK  1024
#define MAX_SB    128

typedef unsigned long long ull;

// ---------------- scratch (static __device__) ----------------
__device__ float4 g_xw4[(size_t)N_NODES * 16];   // dis-premultiplied x@W rows
__device__ float4 g_h4 [(size_t)N_NODES * 16];   // layer-1 result
__device__ float  g_dis[N_NODES];
__device__ int    g_cnt[N_NODES];
__device__ int    g_rowstart[N_NODES + 1];
__device__ int    g_cursor[N_NODES];
__device__ int    g_csr[MAX_E];
__device__ int    g_flag[MAX_SB];

__device__ __forceinline__ uint32_t smem_u32(const void* p) {
    uint32_t a;
    asm("{ .reg .u64 t; cvta.to.shared.u64 t, %1; cvt.u32.u64 %0, t; }"
        : "=r"(a) : "l"(p));
    return a;
}

__device__ __forceinline__ int probe_is64(const int* ei32, int* sflag) {
    if (threadIdx.x == 0) {
        int allz = 1;
        #pragma unroll
        for (int k = 0; k < 64; k++)
            if (ei32[2 * k + 1] != 0) { allz = 0; break; }
        *sflag = allz;
    }
    __syncthreads();
    return *sflag;
}

// ---------------- histogram of dst ----------------
__global__ void k_hist(const int* __restrict__ ei32, int E, int n) {
    __shared__ int sis64;
    int is64 = probe_is64(ei32, &sis64);
    int e = blockIdx.x * blockDim.x + threadIdx.x;
    if (e < E) {
        int d;
        if (is64) d = (int)((const long long*)ei32)[(size_t)E + e];
        else      d = ei32[(size_t)E + e];
        d = d < 0 ? 0 : (d >= n ? n - 1 : d);
        atomicAdd(&g_cnt[d], 1);
    }
}

// ------ single-pass scan (decoupled lookback) ------
__global__ __launch_bounds__(256) void k_scan(int n, int E) {
    __shared__ int s[256];
    __shared__ int sbase;
    const int t   = threadIdx.x;
    const int bid = blockIdx.x;
    const int i0  = bid * SCAN_BLK + t * 4;

    int c[4];
    int sum = 0;
    #pragma unroll
    for (int k = 0; k < 4; k++) {
        int i = i0 + k;
        c[k] = (i < n) ? g_cnt[i] : 0;
        sum += c[k];
        if (i < n) g_dis[i] = rsqrtf((float)c[k] + 1.0f);
    }
    s[t] = sum;
    __syncthreads();
    for (int off = 1; off < 256; off <<= 1) {
        int a = (t >= off) ? s[t - off] : 0;
        __syncthreads();
        s[t] += a;
        __syncthreads();
    }
    int myIncl = s[t];
    int total  = s[255];
    if (t == 0) atomicExch(&g_flag[bid], total + 1);
    int part = 0;
    if (t < bid) {
        int v;
        do { v = atomicAdd(&g_flag[t], 0); } while (v == 0);
        part = v - 1;
    }
    __syncthreads();
    s[t] = part;
    __syncthreads();
    for (int off = 128; off > 0; off >>= 1) {
        if (t < off) s[t] += s[t + off];
        __syncthreads();
    }
    if (t == 0) {
        sbase = s[0];
        if (bid == 0) g_rowstart[n] = E;
    }
    __syncthreads();
    int base = sbase + myIncl - sum;
    #pragma unroll
    for (int k = 0; k < 4; k++) {
        int i = i0 + k;
        if (i < n) {
            g_rowstart[i] = base;
            g_cursor[i]   = base;
            base += c[k];
        }
    }
}

// -------- CSR fill + reset zero-invariants --------
__global__ void k_fill(const int* __restrict__ ei32, int E, int n) {
    __shared__ int sis64;
    int is64 = probe_is64(ei32, &sis64);
    int e = blockIdx.x * blockDim.x + threadIdx.x;
    if (e < E) {
        int s, d;
        if (is64) {
            const long long* ei64 = (const long long*)ei32;
            s = (int)ei64[e];
            d = (int)ei64[(size_t)E + e];
        } else {
            s = ei32[e];
            d = ei32[(size_t)E + e];
        }
        s = s < 0 ? 0 : (s >= n ? n - 1 : s);
        d = d < 0 ? 0 : (d >= n ? n - 1 : d);
        int pos = atomicAdd(&g_cursor[d], 1);
        g_csr[pos] = s;
        g_cnt[d]   = 0;
    }
    if (e < MAX_SB) g_flag[e] = 0;
}

// -------- GEMM via mma.sync bf16 split-precision, cross-term paired --------
// D = x@W with x=xh+xl, W=Wh+Wl (bf16 splits): D = xh@Wh + xh@Wl + xl@Wh.
// A smem: 128 x [xh(0-63)|xl(64-127)] bf16, row stride 272 B.
// B smem: 64 x [Wh|Wl] bf16 (Wt[n][k]=W[k][n]), same stride.
// Mainloop pairs chunks explicitly: kc<4 -> B{kc, kc+4}; kc>=4 -> B{kc-4}.
#define SROW 136   // bf16 elements per padded smem row (272 B)

__global__ __launch_bounds__(256) void k_gemm_mma(
    const float* __restrict__ in_ext, int in_is_h,
    const float* __restrict__ W, int relu, int n)
{
    extern __shared__ char dsm[];
    char* sB = dsm;                       // 64  * 272 = 17408 B
    char* sA = dsm + 64 * (SROW * 2);     // 128 * 272 = 34816 B

    const float* in = in_is_h ? (const float*)g_h4 : in_ext;
    float*       xw = (float*)g_xw4;

    const int tid  = threadIdx.x;
    const int lane = tid & 31;
    const int wid  = tid >> 5;
    const int row0 = blockIdx.x * 128;

    uint32_t sBu = smem_u32(sB);
    uint32_t sAu = smem_u32(sA);

    // ---- fill B: Wt[nn][k] split hi/lo ----
    for (int e = tid; e < 64 * 64; e += 256) {
        int k  = e >> 6;
        int nn = e & 63;
        float w = W[e];
        __nv_bfloat16 hb = __float2bfloat16_rn(w);
        __nv_bfloat16 lb = __float2bfloat16_rn(w - __bfloat162float(hb));
        *(__nv_bfloat16*)(sB + nn * (SROW * 2) + k * 2)        = hb;
        *(__nv_bfloat16*)(sB + nn * (SROW * 2) + (64 + k) * 2) = lb;
    }

    // ---- fill A: row r = tid>>1, cols h*32..h*32+31 ----
    {
        int r  = tid >> 1;
        int h  = tid & 1;
        int gr = row0 + r;
        bool valid = gr < n;
        const float* xr = in + (size_t)gr * 64 + h * 32;
        char* rowp = sA + r * (SROW * 2);
        #pragma unroll
        for (int i = 0; i < 8; i++) {
            float4 f = valid ? *(const float4*)(xr + i * 4)
                             : make_float4(0.f, 0.f, 0.f, 0.f);
            if (relu) {
                f.x = fmaxf(f.x, 0.f); f.y = fmaxf(f.y, 0.f);
                f.z = fmaxf(f.z, 0.f); f.w = fmaxf(f.w, 0.f);
            }
            __nv_bfloat162 h0 = __floats2bfloat162_rn(f.x, f.y);
            __nv_bfloat162 h1 = __floats2bfloat162_rn(f.z, f.w);
            float2 d0 = __bfloat1622float2(h0);
            float2 d1 = __bfloat1622float2(h1);
            __nv_bfloat162 l0 = __floats2bfloat162_rn(f.x - d0.x, f.y - d0.y);
            __nv_bfloat162 l1 = __floats2bfloat162_rn(f.z - d1.x, f.w - d1.y);
            int c = h * 32 + i * 4;
            *(uint32_t*)(rowp + c * 2)              = *(uint32_t*)&h0;
            *(uint32_t*)(rowp + (c + 2) * 2)        = *(uint32_t*)&h1;
            *(uint32_t*)(rowp + (64 + c) * 2)       = *(uint32_t*)&l0;
            *(uint32_t*)(rowp + (64 + c + 2) * 2)   = *(uint32_t*)&l1;
        }
    }
    __syncthreads();

    // ---- mma mainloop: warp = rows r0..r0+15, all 64 cols ----
    const int r0 = wid * 16;
    float c[8][4];
    #pragma unroll
    for (int nt = 0; nt < 8; nt++)
        #pragma unroll
        for (int j = 0; j < 4; j++) c[nt][j] = 0.f;

    uint32_t aRow = (uint32_t)(r0 + (lane & 15));
    uint32_t aKof = (uint32_t)((lane >> 4) * 8);
    uint32_t aAddrBase = sAu + aRow * (SROW * 2) + aKof * 2;
    uint32_t bRowIn = (uint32_t)((lane & 7) + ((lane >> 4) & 1) * 8);
    uint32_t bKof   = (uint32_t)(((lane >> 3) & 1) * 8);

    #pragma unroll
    for (int kc = 0; kc < 8; kc++) {
        uint32_t a0, a1, a2, a3;
        asm volatile("ldmatrix.sync.aligned.m8n8.x4.shared.b16 {%0,%1,%2,%3}, [%4];"
                     : "=r"(a0), "=r"(a1), "=r"(a2), "=r"(a3)
                     : "r"(aAddrBase + (uint32_t)(kc * 16 * 2)));
        const int nPair = (kc < 4) ? 2 : 1;
        #pragma unroll
        for (int bi = 0; bi < 2; bi++) {
            if (bi >= nPair) break;
            int bk = (kc < 4) ? (bi == 0 ? kc : kc + 4) : (kc - 4);
            #pragma unroll
            for (int nt2 = 0; nt2 < 4; nt2++) {
                uint32_t b00, b01, b10, b11;
                uint32_t bAddr = sBu + (uint32_t)(16 * nt2 + bRowIn) * (SROW * 2)
                               + (uint32_t)(bk * 16 + bKof) * 2;
                asm volatile("ldmatrix.sync.aligned.m8n8.x4.shared.b16 {%0,%1,%2,%3}, [%4];"
                             : "=r"(b00), "=r"(b01), "=r"(b10), "=r"(b11)
                             : "r"(bAddr));
                asm volatile(
                    "mma.sync.aligned.m16n8k16.row.col.f32.bf16.bf16.f32 "
                    "{%0,%1,%2,%3}, {%4,%5,%6,%7}, {%8,%9}, {%0,%1,%2,%3};"
                    : "+f"(c[2*nt2][0]), "+f"(c[2*nt2][1]),
                      "+f"(c[2*nt2][2]), "+f"(c[2*nt2][3])
                    : "r"(a0), "r"(a1), "r"(a2), "r"(a3), "r"(b00), "r"(b01));
                asm volatile(
                    "mma.sync.aligned.m16n8k16.row.col.f32.bf16.bf16.f32 "
                    "{%0,%1,%2,%3}, {%4,%5,%6,%7}, {%8,%9}, {%0,%1,%2,%3};"
                    : "+f"(c[2*nt2+1][0]), "+f"(c[2*nt2+1][1]),
                      "+f"(c[2*nt2+1][2]), "+f"(c[2*nt2+1][3])
                    : "r"(a0), "r"(a1), "r"(a2), "r"(a3), "r"(b10), "r"(b11));
            }
        }
    }

    // ---- epilogue: D[g][2t,2t+1] & D[g+8][...]; scale by dis, store -------
    {
        int g = lane >> 2;
        int t2 = (lane & 3) * 2;
        int grLo = row0 + r0 + g;
        int grHi = grLo + 8;
        float dLo = (grLo < n) ? g_dis[grLo] : 0.f;
        float dHi = (grHi < n) ? g_dis[grHi] : 0.f;
        #pragma unroll
        for (int nt = 0; nt < 8; nt++) {
            int col = nt * 8 + t2;
            if (grLo < n)
                *(float2*)&xw[(size_t)grLo * 64 + col] =
                    make_float2(dLo * c[nt][0], dLo * c[nt][1]);
            if (grHi < n)
                *(float2*)&xw[(size_t)grHi * 64 + col] =
                    make_float2(dHi * c[nt][2], dHi * c[nt][3]);
        }
    }
}

// ------- CSR gather: out[d] = dis[d]*(row[d] + sum rows[s_j]) + b ----------
__global__ __launch_bounds__(256) void k_gather(
    const float* __restrict__ bias,
    float* __restrict__ out_ext, int out_is_h, int n)
{
    const float4* xw  = g_xw4;
    float4*       out = out_is_h ? g_h4 : (float4*)out_ext;

    int warp = (blockIdx.x * blockDim.x + threadIdx.x) >> 5;
    if (warp >= n) return;
    int lane = threadIdx.x & 31;
    int half = lane >> 4;
    int q    = lane & 15;

    int   rs   = g_rowstart[warp];
    int   re   = g_rowstart[warp + 1];
    float disd = g_dis[warp];

    float4 acc = make_float4(0.f, 0.f, 0.f, 0.f);
    if (half == 0) acc = xw[(size_t)warp * 16 + q];

    int j = rs + half;
    for (; j + 6 < re; j += 8) {
        int s0 = g_csr[j];
        int s1 = g_csr[j + 2];
        int s2 = g_csr[j + 4];
        int s3 = g_csr[j + 6];
        float4 v0 = xw[(size_t)s0 * 16 + q];
        float4 v1 = xw[(size_t)s1 * 16 + q];
        float4 v2 = xw[(size_t)s2 * 16 + q];
        float4 v3 = xw[(size_t)s3 * 16 + q];
        acc.x += v0.x + v1.x; acc.y += v0.y + v1.y;
        acc.z += v0.z + v1.z; acc.w += v0.w + v1.w;
        acc.x += v2.x + v3.x; acc.y += v2.y + v3.y;
        acc.z += v2.z + v3.z; acc.w += v2.w + v3.w;
    }
    for (; j < re; j += 2) {
        float4 v = xw[(size_t)g_csr[j] * 16 + q];
        acc.x += v.x; acc.y += v.y; acc.z += v.z; acc.w += v.w;
    }
    acc.x += __shfl_xor_sync(0xffffffffu, acc.x, 16);
    acc.y += __shfl_xor_sync(0xffffffffu, acc.y, 16);
    acc.z += __shfl_xor_sync(0xffffffffu, acc.z, 16);
    acc.w += __shfl_xor_sync(0xffffffffu, acc.w, 16);

    if (half == 0) {
        float4 bb = ((const float4*)bias)[q];
        out[(size_t)warp * 16 + q] =
            make_float4(fmaf(disd, acc.x, bb.x), fmaf(disd, acc.y, bb.y),
                        fmaf(disd, acc.z, bb.z), fmaf(disd, acc.w, bb.w));
    }
}

// ---------------- launch ----------------
extern "C" void kernel_launch(void* const* d_in, const int* in_sizes, int n_in,
                              void* d_out, int out_size)
{
    int ix = -1, iei = -1, iw1 = -1, iw2 = -1, ib1 = -1, ib2 = -1;
    for (int i = 0; i < n_in; i++) {
        int s = in_sizes[i];
        if      (s == N_NODES * FDIM) { if (ix  < 0) ix  = i; }
        else if (s == 2 * MAX_E)      { if (iei < 0) iei = i; }
        else if (s == FDIM * FDIM)    { if (iw1 < 0) iw1 = i; else if (iw2 < 0) iw2 = i; }
        else if (s == FDIM)           { if (ib1 < 0) ib1 = i; else if (ib2 < 0) ib2 = i; }
    }
    if (ix < 0 || iei < 0 || iw1 < 0 || iw2 < 0 || ib1 < 0 || ib2 < 0) {
        ix = 0; iei = 1; iw1 = 2; ib1 = 3; iw2 = 4; ib2 = 5;
    }

    const float* x   = (const float*)d_in[ix];
    const int*   ei  = (const int*)d_in[iei];
    const float* W1  = (const float*)d_in[iw1];
    const float* b1  = (const float*)d_in[ib1];
    const float* W2  = (const float*)d_in[iw2];
    const float* b2  = (const float*)d_in[ib2];
    float*       out = (float*)d_out;

    int n = in_sizes[ix] / FDIM;
    int E = in_sizes[iei] / 2;
    if (n > N_NODES) n = N_NODES;
    if (E > MAX_E)   E = MAX_E;

    const int TB = 256;
    const int edgeBlocks = (E + TB - 1) / TB;
    const int nbScan     = (n + SCAN_BLK - 1) / SCAN_BLK;
    const int gthBlocks  = (n + 7) / 8;
    const int nTiles     = (n + 127) / 128;
    const int gemmSmem   = (64 + 128) * (SROW * 2);   // 52224 B

    static int attrSet = 0;
    if (!attrSet) {
        cudaFuncSetAttribute(k_gemm_mma,
            cudaFuncAttributeMaxDynamicSharedMemorySize, gemmSmem);
        attrSet = 1;
    }

    k_hist<<<edgeBlocks, TB>>>(ei, E, n);                           // launch 0
    k_scan<<<nbScan, 256>>>(n, E);                                  // launch 1
    k_fill<<<edgeBlocks, TB>>>(ei, E, n);                           // launch 2

    // layer 1: h = dis*(self + sum rows) + b1, rows = dis*(x@W1)
    k_gemm_mma<<<nTiles, 256, gemmSmem>>>(x, 0, W1, 0, n);          // launch 3
    k_gather  <<<gthBlocks, TB>>>(b1, nullptr, 1, n);               // launch 4

    // layer 2: out = dis*(self + sum rows) + b2, rows = dis*(relu(h)@W2)
    k_gemm_mma<<<nTiles, 256, gemmSmem>>>(nullptr, 1, W2, 1, n);    // launch 5 (ncu)
    k_gather  <<<gthBlocks, TB>>>(b2, out, 0, n);                   // launch 6
}

// round 14
// speedup vs baseline: 1.1653x; 1.0513x over previous
#include <cuda_runtime.h>
#include <cuda_bf16.h>
#include <cstdint>

#define N_NODES   100000
#define FDIM      64
#define MAX_E     1250000
#define SCAN_BLK  1024
#define MAX_SB    128
#define SROW      136   // bf16 elements per padded smem row (272 B)

typedef unsigned long long ull;

// ---------------- scratch (static __device__) ----------------
__device__ float4 g_xw4[(size_t)N_NODES * 16];   // dis-premultiplied x@W rows
__device__ float4 g_h4 [(size_t)N_NODES * 16];   // layer-1 result
__device__ float  g_dis[N_NODES];
__device__ int    g_cnt[N_NODES];
__device__ int    g_rowstart[N_NODES + 1];
__device__ int    g_cursor[N_NODES];
__device__ int    g_csr[MAX_E];
__device__ int    g_flag[MAX_SB];
__device__ float4 g_wt4[2][64 * SROW * 2 / 16];  // pre-split Wt (bf16, smem layout)

__device__ __forceinline__ uint32_t smem_u32(const void* p) {
    uint32_t a;
    asm("{ .reg .u64 t; cvta.to.shared.u64 t, %1; cvt.u32.u64 %0, t; }"
        : "=r"(a) : "l"(p));
    return a;
}

__device__ __forceinline__ int probe_is64(const int* ei32, int* sflag) {
    if (threadIdx.x == 0) {
        int allz = 1;
        #pragma unroll
        for (int k = 0; k < 64; k++)
            if (ei32[2 * k + 1] != 0) { allz = 0; break; }
        *sflag = allz;
    }
    __syncthreads();
    return *sflag;
}

// ---------- W pre-split: Wt[nn][k] hi/lo bf16 in smem-ready layout ---------
__global__ void k_wconv(const float* __restrict__ W1, const float* __restrict__ W2) {
    const float* W = (blockIdx.x == 0) ? W1 : W2;
    __nv_bfloat16* dst = (__nv_bfloat16*)g_wt4[blockIdx.x];
    for (int e = threadIdx.x; e < 64 * 64; e += 256) {
        int k  = e >> 6;
        int nn = e & 63;
        float w = W[e];
        __nv_bfloat16 hb = __float2bfloat16_rn(w);
        __nv_bfloat16 lb = __float2bfloat16_rn(w - __bfloat162float(hb));
        dst[nn * SROW + k]      = hb;
        dst[nn * SROW + 64 + k] = lb;
    }
}

// ---------------- histogram of dst ----------------
__global__ void k_hist(const int* __restrict__ ei32, int E, int n) {
    __shared__ int sis64;
    int is64 = probe_is64(ei32, &sis64);
    int e = blockIdx.x * blockDim.x + threadIdx.x;
    if (e < E) {
        int d;
        if (is64) d = (int)((const long long*)ei32)[(size_t)E + e];
        else      d = ei32[(size_t)E + e];
        d = d < 0 ? 0 : (d >= n ? n - 1 : d);
        atomicAdd(&g_cnt[d], 1);
    }
}

// ------ single-pass scan (decoupled lookback) ------
__global__ __launch_bounds__(256) void k_scan(int n, int E) {
    __shared__ int s[256];
    __shared__ int sbase;
    const int t   = threadIdx.x;
    const int bid = blockIdx.x;
    const int i0  = bid * SCAN_BLK + t * 4;

    int c[4];
    int sum = 0;
    #pragma unroll
    for (int k = 0; k < 4; k++) {
        int i = i0 + k;
        c[k] = (i < n) ? g_cnt[i] : 0;
        sum += c[k];
        if (i < n) g_dis[i] = rsqrtf((float)c[k] + 1.0f);
    }
    s[t] = sum;
    __syncthreads();
    for (int off = 1; off < 256; off <<= 1) {
        int a = (t >= off) ? s[t - off] : 0;
        __syncthreads();
        s[t] += a;
        __syncthreads();
    }
    int myIncl = s[t];
    int total  = s[255];
    if (t == 0) atomicExch(&g_flag[bid], total + 1);
    int part = 0;
    if (t < bid) {
        int v;
        do { v = atomicAdd(&g_flag[t], 0); } while (v == 0);
        part = v - 1;
    }
    __syncthreads();
    s[t] = part;
    __syncthreads();
    for (int off = 128; off > 0; off >>= 1) {
        if (t < off) s[t] += s[t + off];
        __syncthreads();
    }
    if (t == 0) {
        sbase = s[0];
        if (bid == 0) g_rowstart[n] = E;
    }
    __syncthreads();
    int base = sbase + myIncl - sum;
    #pragma unroll
    for (int k = 0; k < 4; k++) {
        int i = i0 + k;
        if (i < n) {
            g_rowstart[i] = base;
            g_cursor[i]   = base;
            base += c[k];
        }
    }
}

// -------- CSR fill + reset zero-invariants --------
__global__ void k_fill(const int* __restrict__ ei32, int E, int n) {
    __shared__ int sis64;
    int is64 = probe_is64(ei32, &sis64);
    int e = blockIdx.x * blockDim.x + threadIdx.x;
    if (e < E) {
        int s, d;
        if (is64) {
            const long long* ei64 = (const long long*)ei32;
            s = (int)ei64[e];
            d = (int)ei64[(size_t)E + e];
        } else {
            s = ei32[e];
            d = ei32[(size_t)E + e];
        }
        s = s < 0 ? 0 : (s >= n ? n - 1 : s);
        d = d < 0 ? 0 : (d >= n ? n - 1 : d);
        int pos = atomicAdd(&g_cursor[d], 1);
        g_csr[pos] = s;
        g_cnt[d]   = 0;
    }
    if (e < MAX_SB) g_flag[e] = 0;
}

// -------- GEMM via mma.sync bf16 split, persistent B fragments -------------
// D = xh@Wh + xh@Wl + xl@Wh. Block: 128x64; warp = 32 rows x 32 cols (4x2).
// B fragments preloaded once per warp (8 chunks x 2 n16-groups = 64 regs).
__global__ __launch_bounds__(256) void k_gemm_mma(
    const float* __restrict__ in_ext, int in_is_h,
    int widx, int relu, int n)
{
    extern __shared__ char dsm[];
    char* sB = dsm;                       // 64  * 272 = 17408 B
    char* sA = dsm + 64 * (SROW * 2);     // 128 * 272 = 34816 B

    const float* in = in_is_h ? (const float*)g_h4 : in_ext;
    float*       xw = (float*)g_xw4;

    const int tid  = threadIdx.x;
    const int lane = tid & 31;
    const int wid  = tid >> 5;
    const int row0 = blockIdx.x * 128;

    uint32_t sBu = smem_u32(sB);
    uint32_t sAu = smem_u32(sA);

    // ---- copy pre-split B (17408 B = 1088 float4) ----
    {
        const float4* src = g_wt4[widx];
        float4*       dst = (float4*)sB;
        #pragma unroll
        for (int i = 0; i < 4; i++) dst[tid + i * 256] = src[tid + i * 256];
        if (tid < 1088 - 1024) dst[tid + 1024] = src[tid + 1024];
    }

    // ---- fill A: row r = tid>>1, cols h*32..h*32+31 ----
    {
        int r  = tid >> 1;
        int h  = tid & 1;
        int gr = row0 + r;
        bool valid = gr < n;
        const float* xr = in + (size_t)gr * 64 + h * 32;
        char* rowp = sA + r * (SROW * 2);
        #pragma unroll
        for (int i = 0; i < 8; i++) {
            float4 f = valid ? *(const float4*)(xr + i * 4)
                             : make_float4(0.f, 0.f, 0.f, 0.f);
            if (relu) {
                f.x = fmaxf(f.x, 0.f); f.y = fmaxf(f.y, 0.f);
                f.z = fmaxf(f.z, 0.f); f.w = fmaxf(f.w, 0.f);
            }
            __nv_bfloat162 h0 = __floats2bfloat162_rn(f.x, f.y);
            __nv_bfloat162 h1 = __floats2bfloat162_rn(f.z, f.w);
            float2 d0 = __bfloat1622float2(h0);
            float2 d1 = __bfloat1622float2(h1);
            __nv_bfloat162 l0 = __floats2bfloat162_rn(f.x - d0.x, f.y - d0.y);
            __nv_bfloat162 l1 = __floats2bfloat162_rn(f.z - d1.x, f.w - d1.y);
            int c = h * 32 + i * 4;
            *(uint32_t*)(rowp + c * 2)              = *(uint32_t*)&h0;
            *(uint32_t*)(rowp + (c + 2) * 2)        = *(uint32_t*)&h1;
            *(uint32_t*)(rowp + (64 + c) * 2)       = *(uint32_t*)&l0;
            *(uint32_t*)(rowp + (64 + c + 2) * 2)   = *(uint32_t*)&l1;
        }
    }
    __syncthreads();

    const int rowG = wid >> 1;            // 0..3 (32 rows each)
    const int colG = wid & 1;             // 0..1 (32 cols each)
    const int r0   = rowG * 32;
    const int c0   = colG * 32;

    // ---- preload all B fragments for this warp's 32 cols ----
    uint32_t bRowIn = (uint32_t)((lane & 7) + ((lane >> 4) & 1) * 8);
    uint32_t bKof   = (uint32_t)(((lane >> 3) & 1) * 8);
    uint32_t bf[8][2][4];
    #pragma unroll
    for (int ch = 0; ch < 8; ch++)
        #pragma unroll
        for (int g16 = 0; g16 < 2; g16++) {
            uint32_t bAddr = sBu
                + (uint32_t)(c0 + g16 * 16 + bRowIn) * (SROW * 2)
                + (uint32_t)(ch * 16 + bKof) * 2;
            asm volatile("ldmatrix.sync.aligned.m8n8.x4.shared.b16 {%0,%1,%2,%3}, [%4];"
                         : "=r"(bf[ch][g16][0]), "=r"(bf[ch][g16][1]),
                           "=r"(bf[ch][g16][2]), "=r"(bf[ch][g16][3])
                         : "r"(bAddr));
        }

    float c[2][4][4];                     // [rowtile][n8][4]
    #pragma unroll
    for (int rt = 0; rt < 2; rt++)
        #pragma unroll
        for (int nt = 0; nt < 4; nt++)
            #pragma unroll
            for (int j = 0; j < 4; j++) c[rt][nt][j] = 0.f;

    uint32_t aLane = (uint32_t)(lane & 15);
    uint32_t aKof  = (uint32_t)((lane >> 4) * 8);

    #pragma unroll
    for (int kc = 0; kc < 8; kc++) {
        uint32_t a[2][4];
        #pragma unroll
        for (int rt = 0; rt < 2; rt++) {
            uint32_t aAddr = sAu
                + (uint32_t)(r0 + rt * 16 + aLane) * (SROW * 2)
                + (uint32_t)(kc * 16 + aKof) * 2;
            asm volatile("ldmatrix.sync.aligned.m8n8.x4.shared.b16 {%0,%1,%2,%3}, [%4];"
                         : "=r"(a[rt][0]), "=r"(a[rt][1]),
                           "=r"(a[rt][2]), "=r"(a[rt][3])
                         : "r"(aAddr));
        }
        const int nPair = (kc < 4) ? 2 : 1;
        #pragma unroll
        for (int bi = 0; bi < 2; bi++) {
            if (bi >= nPair) break;
            int bc = (kc < 4) ? (bi == 0 ? kc : kc + 4) : (kc - 4);
            #pragma unroll
            for (int rt = 0; rt < 2; rt++)
                #pragma unroll
                for (int g16 = 0; g16 < 2; g16++) {
                    asm volatile(
                        "mma.sync.aligned.m16n8k16.row.col.f32.bf16.bf16.f32 "
                        "{%0,%1,%2,%3}, {%4,%5,%6,%7}, {%8,%9}, {%0,%1,%2,%3};"
                        : "+f"(c[rt][g16*2][0]), "+f"(c[rt][g16*2][1]),
                          "+f"(c[rt][g16*2][2]), "+f"(c[rt][g16*2][3])
                        : "r"(a[rt][0]), "r"(a[rt][1]), "r"(a[rt][2]), "r"(a[rt][3]),
                          "r"(bf[bc][g16][0]), "r"(bf[bc][g16][1]));
                    asm volatile(
                        "mma.sync.aligned.m16n8k16.row.col.f32.bf16.bf16.f32 "
                        "{%0,%1,%2,%3}, {%4,%5,%6,%7}, {%8,%9}, {%0,%1,%2,%3};"
                        : "+f"(c[rt][g16*2+1][0]), "+f"(c[rt][g16*2+1][1]),
                          "+f"(c[rt][g16*2+1][2]), "+f"(c[rt][g16*2+1][3])
                        : "r"(a[rt][0]), "r"(a[rt][1]), "r"(a[rt][2]), "r"(a[rt][3]),
                          "r"(bf[bc][g16][2]), "r"(bf[bc][g16][3]));
                }
        }
    }

    // ---- epilogue ----
    {
        int g  = lane >> 2;
        int t2 = (lane & 3) * 2;
        #pragma unroll
        for (int rt = 0; rt < 2; rt++) {
            int grLo = row0 + r0 + rt * 16 + g;
            int grHi = grLo + 8;
            float dLo = (grLo < n) ? g_dis[grLo] : 0.f;
            float dHi = (grHi < n) ? g_dis[grHi] : 0.f;
            #pragma unroll
            for (int nt = 0; nt < 4; nt++) {
                int col = c0 + nt * 8 + t2;
                if (grLo < n)
                    *(float2*)&xw[(size_t)grLo * 64 + col] =
                        make_float2(dLo * c[rt][nt][0], dLo * c[rt][nt][1]);
                if (grHi < n)
                    *(float2*)&xw[(size_t)grHi * 64 + col] =
                        make_float2(dHi * c[rt][nt][2], dHi * c[rt][nt][3]);
            }
        }
    }
}

// ------- CSR gather: out[d] = dis[d]*(row[d] + sum rows[s_j]) + b ----------
__global__ __launch_bounds__(256) void k_gather(
    const float* __restrict__ bias,
    float* __restrict__ out_ext, int out_is_h, int n)
{
    const float4* xw  = g_xw4;
    float4*       out = out_is_h ? g_h4 : (float4*)out_ext;

    int warp = (blockIdx.x * blockDim.x + threadIdx.x) >> 5;
    if (warp >= n) return;
    int lane = threadIdx.x & 31;
    int half = lane >> 4;
    int q    = lane & 15;

    int   rs   = g_rowstart[warp];
    int   re   = g_rowstart[warp + 1];
    float disd = g_dis[warp];

    float4 acc = make_float4(0.f, 0.f, 0.f, 0.f);
    if (half == 0) acc = xw[(size_t)warp * 16 + q];

    int j = rs + half;
    for (; j + 6 < re; j += 8) {
        int s0 = g_csr[j];
        int s1 = g_csr[j + 2];
        int s2 = g_csr[j + 4];
        int s3 = g_csr[j + 6];
        float4 v0 = xw[(size_t)s0 * 16 + q];
        float4 v1 = xw[(size_t)s1 * 16 + q];
        float4 v2 = xw[(size_t)s2 * 16 + q];
        float4 v3 = xw[(size_t)s3 * 16 + q];
        acc.x += v0.x + v1.x; acc.y += v0.y + v1.y;
        acc.z += v0.z + v1.z; acc.w += v0.w + v1.w;
        acc.x += v2.x + v3.x; acc.y += v2.y + v3.y;
        acc.z += v2.z + v3.z; acc.w += v2.w + v3.w;
    }
    for (; j < re; j += 2) {
        float4 v = xw[(size_t)g_csr[j] * 16 + q];
        acc.x += v.x; acc.y += v.y; acc.z += v.z; acc.w += v.w;
    }
    acc.x += __shfl_xor_sync(0xffffffffu, acc.x, 16);
    acc.y += __shfl_xor_sync(0xffffffffu, acc.y, 16);
    acc.z += __shfl_xor_sync(0xffffffffu, acc.z, 16);
    acc.w += __shfl_xor_sync(0xffffffffu, acc.w, 16);

    if (half == 0) {
        float4 bb = ((const float4*)bias)[q];
        out[(size_t)warp * 16 + q] =
            make_float4(fmaf(disd, acc.x, bb.x), fmaf(disd, acc.y, bb.y),
                        fmaf(disd, acc.z, bb.z), fmaf(disd, acc.w, bb.w));
    }
}

// ---------------- launch ----------------
extern "C" void kernel_launch(void* const* d_in, const int* in_sizes, int n_in,
                              void* d_out, int out_size)
{
    int ix = -1, iei = -1, iw1 = -1, iw2 = -1, ib1 = -1, ib2 = -1;
    for (int i = 0; i < n_in; i++) {
        int s = in_sizes[i];
        if      (s == N_NODES * FDIM) { if (ix  < 0) ix  = i; }
        else if (s == 2 * MAX_E)      { if (iei < 0) iei = i; }
        else if (s == FDIM * FDIM)    { if (iw1 < 0) iw1 = i; else if (iw2 < 0) iw2 = i; }
        else if (s == FDIM)           { if (ib1 < 0) ib1 = i; else if (ib2 < 0) ib2 = i; }
    }
    if (ix < 0 || iei < 0 || iw1 < 0 || iw2 < 0 || ib1 < 0 || ib2 < 0) {
        ix = 0; iei = 1; iw1 = 2; ib1 = 3; iw2 = 4; ib2 = 5;
    }

    const float* x   = (const float*)d_in[ix];
    const int*   ei  = (const int*)d_in[iei];
    const float* W1  = (const float*)d_in[iw1];
    const float* b1  = (const float*)d_in[ib1];
    const float* W2  = (const float*)d_in[iw2];
    const float* b2  = (const float*)d_in[ib2];
    float*       out = (float*)d_out;

    int n = in_sizes[ix] / FDIM;
    int E = in_sizes[iei] / 2;
    if (n > N_NODES) n = N_NODES;
    if (E > MAX_E)   E = MAX_E;

    const int TB = 256;
    const int edgeBlocks = (E + TB - 1) / TB;
    const int nbScan     = (n + SCAN_BLK - 1) / SCAN_BLK;
    const int gthBlocks  = (n + 7) / 8;
    const int nTiles     = (n + 127) / 128;
    const int gemmSmem   = (64 + 128) * (SROW * 2);   // 52224 B

    static int attrSet = 0;
    if (!attrSet) {
        cudaFuncSetAttribute(k_gemm_mma,
            cudaFuncAttributeMaxDynamicSharedMemorySize, gemmSmem);
        attrSet = 1;
    }

    k_wconv<<<2, 256>>>(W1, W2);                                    // launch 0
    k_hist<<<edgeBlocks, TB>>>(ei, E, n);                           // launch 1
    k_scan<<<nbScan, 256>>>(n, E);                                  // launch 2
    k_fill<<<edgeBlocks, TB>>>(ei, E, n);                           // launch 3

    // layer 1: h = dis*(self + sum rows) + b1, rows = dis*(x@W1)
    k_gemm_mma<<<nTiles, 256, gemmSmem>>>(x, 0, 0, 0, n);           // launch 4
    k_gather  <<<gthBlocks, TB>>>(b1, nullptr, 1, n);               // launch 5 (ncu)

    // layer 2: out = dis*(self + sum rows) + b2, rows = dis*(relu(h)@W2)
    k_gemm_mma<<<nTiles, 256, gemmSmem>>>(nullptr, 1, 1, 1, n);     // launch 6
    k_gather  <<<gthBlocks, TB>>>(b2, out, 0, n);                   // launch 7
}

// round 15
// speedup vs baseline: 1.2034x; 1.0327x over previous
#include <cuda_runtime.h>
#include <cuda_bf16.h>
#include <cstdint>

#define N_NODES   100000
#define FDIM      64
#define MAX_E     1250000
#define SCAN_BLK  1024
#define MAX_SB    128
#define SROW      136   // bf16 elements per padded smem row (272 B)

typedef unsigned long long ull;

// ---------------- scratch (static __device__) ----------------
__device__ float4 g_xw4[(size_t)N_NODES * 16];   // dis-premultiplied x@W rows
__device__ float4 g_h4 [(size_t)N_NODES * 16];   // layer-1 result
__device__ float  g_dis[N_NODES];
__device__ int    g_cnt[N_NODES];
__device__ int    g_rowstart[N_NODES + 1];
__device__ int    g_cursor[N_NODES];
__device__ int    g_csr[MAX_E];
__device__ int    g_flag[MAX_SB];
__device__ float4 g_wt4[2][64 * SROW * 2 / 16];  // pre-split Wt (bf16, smem layout)

__device__ __forceinline__ uint32_t smem_u32(const void* p) {
    uint32_t a;
    asm("{ .reg .u64 t; cvta.to.shared.u64 t, %1; cvt.u32.u64 %0, t; }"
        : "=r"(a) : "l"(p));
    return a;
}

__device__ __forceinline__ int probe_is64(const int* ei32, int* sflag) {
    if (threadIdx.x == 0) {
        int allz = 1;
        #pragma unroll
        for (int k = 0; k < 64; k++)
            if (ei32[2 * k + 1] != 0) { allz = 0; break; }
        *sflag = allz;
    }
    __syncthreads();
    return *sflag;
}

// ---------- W pre-split: Wt[nn][k] hi/lo bf16 in smem-ready layout ---------
__global__ void k_wconv(const float* __restrict__ W1, const float* __restrict__ W2) {
    const float* W = (blockIdx.x == 0) ? W1 : W2;
    __nv_bfloat16* dst = (__nv_bfloat16*)g_wt4[blockIdx.x];
    for (int e = threadIdx.x; e < 64 * 64; e += 256) {
        int k  = e >> 6;
        int nn = e & 63;
        float w = W[e];
        __nv_bfloat16 hb = __float2bfloat16_rn(w);
        __nv_bfloat16 lb = __float2bfloat16_rn(w - __bfloat162float(hb));
        dst[nn * SROW + k]      = hb;
        dst[nn * SROW + 64 + k] = lb;
    }
}

// ---------------- histogram of dst ----------------
__global__ void k_hist(const int* __restrict__ ei32, int E, int n) {
    __shared__ int sis64;
    int is64 = probe_is64(ei32, &sis64);
    int e = blockIdx.x * blockDim.x + threadIdx.x;
    if (e < E) {
        int d;
        if (is64) d = (int)((const long long*)ei32)[(size_t)E + e];
        else      d = ei32[(size_t)E + e];
        d = d < 0 ? 0 : (d >= n ? n - 1 : d);
        atomicAdd(&g_cnt[d], 1);
    }
}

// ------ single-pass scan (decoupled lookback) ------
__global__ __launch_bounds__(256) void k_scan(int n, int E) {
    __shared__ int s[256];
    __shared__ int sbase;
    const int t   = threadIdx.x;
    const int bid = blockIdx.x;
    const int i0  = bid * SCAN_BLK + t * 4;

    int c[4];
    int sum = 0;
    #pragma unroll
    for (int k = 0; k < 4; k++) {
        int i = i0 + k;
        c[k] = (i < n) ? g_cnt[i] : 0;
        sum += c[k];
        if (i < n) g_dis[i] = rsqrtf((float)c[k] + 1.0f);
    }
    s[t] = sum;
    __syncthreads();
    for (int off = 1; off < 256; off <<= 1) {
        int a = (t >= off) ? s[t - off] : 0;
        __syncthreads();
        s[t] += a;
        __syncthreads();
    }
    int myIncl = s[t];
    int total  = s[255];
    if (t == 0) atomicExch(&g_flag[bid], total + 1);
    int part = 0;
    if (t < bid) {
        int v;
        do { v = atomicAdd(&g_flag[t], 0); } while (v == 0);
        part = v - 1;
    }
    __syncthreads();
    s[t] = part;
    __syncthreads();
    for (int off = 128; off > 0; off >>= 1) {
        if (t < off) s[t] += s[t + off];
        __syncthreads();
    }
    if (t == 0) {
        sbase = s[0];
        if (bid == 0) g_rowstart[n] = E;
    }
    __syncthreads();
    int base = sbase + myIncl - sum;
    #pragma unroll
    for (int k = 0; k < 4; k++) {
        int i = i0 + k;
        if (i < n) {
            g_rowstart[i] = base;
            g_cursor[i]   = base;
            base += c[k];
        }
    }
}

// -------- CSR fill + reset zero-invariants --------
__global__ void k_fill(const int* __restrict__ ei32, int E, int n) {
    __shared__ int sis64;
    int is64 = probe_is64(ei32, &sis64);
    int e = blockIdx.x * blockDim.x + threadIdx.x;
    if (e < E) {
        int s, d;
        if (is64) {
            const long long* ei64 = (const long long*)ei32;
            s = (int)ei64[e];
            d = (int)ei64[(size_t)E + e];
        } else {
            s = ei32[e];
            d = ei32[(size_t)E + e];
        }
        s = s < 0 ? 0 : (s >= n ? n - 1 : s);
        d = d < 0 ? 0 : (d >= n ? n - 1 : d);
        int pos = atomicAdd(&g_cursor[d], 1);
        g_csr[pos] = s;
        g_cnt[d]   = 0;
    }
    if (e < MAX_SB) g_flag[e] = 0;
}

// -------- GEMM via mma.sync bf16 split, persistent B fragments -------------
__global__ __launch_bounds__(256) void k_gemm_mma(
    const float* __restrict__ in_ext, int in_is_h,
    int widx, int relu, int n)
{
    extern __shared__ char dsm[];
    char* sB = dsm;                       // 64  * 272 = 17408 B
    char* sA = dsm + 64 * (SROW * 2);     // 128 * 272 = 34816 B

    const float* in = in_is_h ? (const float*)g_h4 : in_ext;
    float*       xw = (float*)g_xw4;

    const int tid  = threadIdx.x;
    const int lane = tid & 31;
    const int wid  = tid >> 5;
    const int row0 = blockIdx.x * 128;

    uint32_t sBu = smem_u32(sB);
    uint32_t sAu = smem_u32(sA);

    // ---- copy pre-split B (17408 B = 1088 float4) ----
    {
        const float4* src = g_wt4[widx];
        float4*       dst = (float4*)sB;
        #pragma unroll
        for (int i = 0; i < 4; i++) dst[tid + i * 256] = src[tid + i * 256];
        if (tid < 1088 - 1024) dst[tid + 1024] = src[tid + 1024];
    }

    // ---- fill A: row r = tid>>1, cols h*32..h*32+31 ----
    {
        int r  = tid >> 1;
        int h  = tid & 1;
        int gr = row0 + r;
        bool valid = gr < n;
        const float* xr = in + (size_t)gr * 64 + h * 32;
        char* rowp = sA + r * (SROW * 2);
        #pragma unroll
        for (int i = 0; i < 8; i++) {
            float4 f = valid ? *(const float4*)(xr + i * 4)
                             : make_float4(0.f, 0.f, 0.f, 0.f);
            if (relu) {
                f.x = fmaxf(f.x, 0.f); f.y = fmaxf(f.y, 0.f);
                f.z = fmaxf(f.z, 0.f); f.w = fmaxf(f.w, 0.f);
            }
            __nv_bfloat162 h0 = __floats2bfloat162_rn(f.x, f.y);
            __nv_bfloat162 h1 = __floats2bfloat162_rn(f.z, f.w);
            float2 d0 = __bfloat1622float2(h0);
            float2 d1 = __bfloat1622float2(h1);
            __nv_bfloat162 l0 = __floats2bfloat162_rn(f.x - d0.x, f.y - d0.y);
            __nv_bfloat162 l1 = __floats2bfloat162_rn(f.z - d1.x, f.w - d1.y);
            int c = h * 32 + i * 4;
            *(uint32_t*)(rowp + c * 2)              = *(uint32_t*)&h0;
            *(uint32_t*)(rowp + (c + 2) * 2)        = *(uint32_t*)&h1;
            *(uint32_t*)(rowp + (64 + c) * 2)       = *(uint32_t*)&l0;
            *(uint32_t*)(rowp + (64 + c + 2) * 2)   = *(uint32_t*)&l1;
        }
    }
    __syncthreads();

    const int rowG = wid >> 1;
    const int colG = wid & 1;
    const int r0   = rowG * 32;
    const int c0   = colG * 32;

    // ---- preload all B fragments for this warp's 32 cols ----
    uint32_t bRowIn = (uint32_t)((lane & 7) + ((lane >> 4) & 1) * 8);
    uint32_t bKof   = (uint32_t)(((lane >> 3) & 1) * 8);
    uint32_t bf[8][2][4];
    #pragma unroll
    for (int ch = 0; ch < 8; ch++)
        #pragma unroll
        for (int g16 = 0; g16 < 2; g16++) {
            uint32_t bAddr = sBu
                + (uint32_t)(c0 + g16 * 16 + bRowIn) * (SROW * 2)
                + (uint32_t)(ch * 16 + bKof) * 2;
            asm volatile("ldmatrix.sync.aligned.m8n8.x4.shared.b16 {%0,%1,%2,%3}, [%4];"
                         : "=r"(bf[ch][g16][0]), "=r"(bf[ch][g16][1]),
                           "=r"(bf[ch][g16][2]), "=r"(bf[ch][g16][3])
                         : "r"(bAddr));
        }

    float c[2][4][4];
    #pragma unroll
    for (int rt = 0; rt < 2; rt++)
        #pragma unroll
        for (int nt = 0; nt < 4; nt++)
            #pragma unroll
            for (int j = 0; j < 4; j++) c[rt][nt][j] = 0.f;

    uint32_t aLane = (uint32_t)(lane & 15);
    uint32_t aKof  = (uint32_t)((lane >> 4) * 8);

    #pragma unroll
    for (int kc = 0; kc < 8; kc++) {
        uint32_t a[2][4];
        #pragma unroll
        for (int rt = 0; rt < 2; rt++) {
            uint32_t aAddr = sAu
                + (uint32_t)(r0 + rt * 16 + aLane) * (SROW * 2)
                + (uint32_t)(kc * 16 + aKof) * 2;
            asm volatile("ldmatrix.sync.aligned.m8n8.x4.shared.b16 {%0,%1,%2,%3}, [%4];"
                         : "=r"(a[rt][0]), "=r"(a[rt][1]),
                           "=r"(a[rt][2]), "=r"(a[rt][3])
                         : "r"(aAddr));
        }
        const int nPair = (kc < 4) ? 2 : 1;
        #pragma unroll
        for (int bi = 0; bi < 2; bi++) {
            if (bi >= nPair) break;
            int bc = (kc < 4) ? (bi == 0 ? kc : kc + 4) : (kc - 4);
            #pragma unroll
            for (int rt = 0; rt < 2; rt++)
                #pragma unroll
                for (int g16 = 0; g16 < 2; g16++) {
                    asm volatile(
                        "mma.sync.aligned.m16n8k16.row.col.f32.bf16.bf16.f32 "
                        "{%0,%1,%2,%3}, {%4,%5,%6,%7}, {%8,%9}, {%0,%1,%2,%3};"
                        : "+f"(c[rt][g16*2][0]), "+f"(c[rt][g16*2][1]),
                          "+f"(c[rt][g16*2][2]), "+f"(c[rt][g16*2][3])
                        : "r"(a[rt][0]), "r"(a[rt][1]), "r"(a[rt][2]), "r"(a[rt][3]),
                          "r"(bf[bc][g16][0]), "r"(bf[bc][g16][1]));
                    asm volatile(
                        "mma.sync.aligned.m16n8k16.row.col.f32.bf16.bf16.f32 "
                        "{%0,%1,%2,%3}, {%4,%5,%6,%7}, {%8,%9}, {%0,%1,%2,%3};"
                        : "+f"(c[rt][g16*2+1][0]), "+f"(c[rt][g16*2+1][1]),
                          "+f"(c[rt][g16*2+1][2]), "+f"(c[rt][g16*2+1][3])
                        : "r"(a[rt][0]), "r"(a[rt][1]), "r"(a[rt][2]), "r"(a[rt][3]),
                          "r"(bf[bc][g16][2]), "r"(bf[bc][g16][3]));
                }
        }
    }

    // ---- epilogue ----
    {
        int g  = lane >> 2;
        int t2 = (lane & 3) * 2;
        #pragma unroll
        for (int rt = 0; rt < 2; rt++) {
            int grLo = row0 + r0 + rt * 16 + g;
            int grHi = grLo + 8;
            float dLo = (grLo < n) ? g_dis[grLo] : 0.f;
            float dHi = (grHi < n) ? g_dis[grHi] : 0.f;
            #pragma unroll
            for (int nt = 0; nt < 4; nt++) {
                int col = c0 + nt * 8 + t2;
                if (grLo < n)
                    *(float2*)&xw[(size_t)grLo * 64 + col] =
                        make_float2(dLo * c[rt][nt][0], dLo * c[rt][nt][1]);
                if (grHi < n)
                    *(float2*)&xw[(size_t)grHi * 64 + col] =
                        make_float2(dHi * c[rt][nt][2], dHi * c[rt][nt][3]);
            }
        }
    }
}

// ------- CSR gather: out[d] = dis[d]*(row[d] + sum rows[s_j]) + b ----------
__global__ __launch_bounds__(256) void k_gather(
    const float* __restrict__ bias,
    float* __restrict__ out_ext, int out_is_h, int n)
{
    const float4* xw  = g_xw4;
    float4*       out = out_is_h ? g_h4 : (float4*)out_ext;

    int warp = (blockIdx.x * blockDim.x + threadIdx.x) >> 5;
    if (warp >= n) return;
    int lane = threadIdx.x & 31;
    int half = lane >> 4;
    int q    = lane & 15;

    int   rs   = g_rowstart[warp];
    int   re   = g_rowstart[warp + 1];
    float disd = g_dis[warp];

    float4 acc = make_float4(0.f, 0.f, 0.f, 0.f);
    if (half == 0) acc = xw[(size_t)warp * 16 + q];

    int j = rs + half;
    for (; j + 6 < re; j += 8) {
        int s0 = g_csr[j];
        int s1 = g_csr[j + 2];
        int s2 = g_csr[j + 4];
        int s3 = g_csr[j + 6];
        float4 v0 = xw[(size_t)s0 * 16 + q];
        float4 v1 = xw[(size_t)s1 * 16 + q];
        float4 v2 = xw[(size_t)s2 * 16 + q];
        float4 v3 = xw[(size_t)s3 * 16 + q];
        acc.x += v0.x + v1.x; acc.y += v0.y + v1.y;
        acc.z += v0.z + v1.z; acc.w += v0.w + v1.w;
        acc.x += v2.x + v3.x; acc.y += v2.y + v3.y;
        acc.z += v2.z + v3.z; acc.w += v2.w + v3.w;
    }
    for (; j < re; j += 2) {
        float4 v = xw[(size_t)g_csr[j] * 16 + q];
        acc.x += v.x; acc.y += v.y; acc.z += v.z; acc.w += v.w;
    }
    acc.x += __shfl_xor_sync(0xffffffffu, acc.x, 16);
    acc.y += __shfl_xor_sync(0xffffffffu, acc.y, 16);
    acc.z += __shfl_xor_sync(0xffffffffu, acc.z, 16);
    acc.w += __shfl_xor_sync(0xffffffffu, acc.w, 16);

    if (half == 0) {
        float4 bb = ((const float4*)bias)[q];
        out[(size_t)warp * 16 + q] =
            make_float4(fmaf(disd, acc.x, bb.x), fmaf(disd, acc.y, bb.y),
                        fmaf(disd, acc.z, bb.z), fmaf(disd, acc.w, bb.w));
    }
}

// ---------------- launch ----------------
extern "C" void kernel_launch(void* const* d_in, const int* in_sizes, int n_in,
                              void* d_out, int out_size)
{
    int ix = -1, iei = -1, iw1 = -1, iw2 = -1, ib1 = -1, ib2 = -1;
    for (int i = 0; i < n_in; i++) {
        int s = in_sizes[i];
        if      (s == N_NODES * FDIM) { if (ix  < 0) ix  = i; }
        else if (s == 2 * MAX_E)      { if (iei < 0) iei = i; }
        else if (s == FDIM * FDIM)    { if (iw1 < 0) iw1 = i; else if (iw2 < 0) iw2 = i; }
        else if (s == FDIM)           { if (ib1 < 0) ib1 = i; else if (ib2 < 0) ib2 = i; }
    }
    if (ix < 0 || iei < 0 || iw1 < 0 || iw2 < 0 || ib1 < 0 || ib2 < 0) {
        ix = 0; iei = 1; iw1 = 2; ib1 = 3; iw2 = 4; ib2 = 5;
    }

    const float* x   = (const float*)d_in[ix];
    const int*   ei  = (const int*)d_in[iei];
    const float* W1  = (const float*)d_in[iw1];
    const float* b1  = (const float*)d_in[ib1];
    const float* W2  = (const float*)d_in[iw2];
    const float* b2  = (const float*)d_in[ib2];
    float*       out = (float*)d_out;

    int n = in_sizes[ix] / FDIM;
    int E = in_sizes[iei] / 2;
    if (n > N_NODES) n = N_NODES;
    if (E > MAX_E)   E = MAX_E;

    const int TB = 256;
    const int edgeBlocks = (E + TB - 1) / TB;
    const int nbScan     = (n + SCAN_BLK - 1) / SCAN_BLK;
    const int gthBlocks  = (n + 7) / 8;
    const int nTiles     = (n + 127) / 128;
    const int gemmSmem   = (64 + 128) * (SROW * 2);   // 52224 B

    static int attrSet = 0;
    static cudaStream_t s2;
    static cudaEvent_t evFork, evJoin;
    if (!attrSet) {
        cudaFuncSetAttribute(k_gemm_mma,
            cudaFuncAttributeMaxDynamicSharedMemorySize, gemmSmem);
        cudaStreamCreateWithFlags(&s2, cudaStreamNonBlocking);
        cudaEventCreateWithFlags(&evFork, cudaEventDisableTiming);
        cudaEventCreateWithFlags(&evJoin, cudaEventDisableTiming);
        attrSet = 1;
    }

    k_wconv<<<2, 256>>>(W1, W2);
    k_hist<<<edgeBlocks, TB>>>(ei, E, n);
    k_scan<<<nbScan, 256>>>(n, E);

    // fork: k_fill (CSR build) runs concurrently with layer-1 GEMM
    cudaEventRecord(evFork, 0);
    cudaStreamWaitEvent(s2, evFork, 0);
    k_fill<<<edgeBlocks, TB, 0, s2>>>(ei, E, n);
    cudaEventRecord(evJoin, s2);

    // layer 1 GEMM (independent of CSR) overlaps with fill
    k_gemm_mma<<<nTiles, 256, gemmSmem>>>(x, 0, 0, 0, n);

    // join: gather needs both CSR (fill) and rows (gemm)
    cudaStreamWaitEvent(0, evJoin, 0);
    k_gather<<<gthBlocks, TB>>>(b1, nullptr, 1, n);

    // layer 2
    k_gemm_mma<<<nTiles, 256, gemmSmem>>>(nullptr, 1, 1, 1, n);
    k_gather<<<gthBlocks, TB>>>(b2, out, 0, n);
}